// round 7
// baseline (speedup 1.0000x reference)
#include <cuda_runtime.h>
#include <cuda_bf16.h>

#define N_ROWS 16384
#define N_COLS 4096
#define MARGIN 0.1f
#define THREADS 256
#define GRID 592                      // 4 CTAs/SM x 148 SMs: balanced single wave
#define NWARP (THREADS / 32)

// Scratch (device globals: no allocation).
__device__ float g_partial[GRID];
__device__ unsigned int g_count = 0;

__global__ void __launch_bounds__(THREADS, 4) mm_pipe_kernel(
    const float* __restrict__ cossim,
    const int* __restrict__ target,
    float* __restrict__ out)
{
    const int bid  = blockIdx.x;
    const int t    = threadIdx.x;
    const int lane = t & 31;
    const int wid  = t >> 5;

    __shared__ float s_corr[2];
    __shared__ float s_warp[NWARP];
    __shared__ unsigned int s_ticket;

    // ---- Preload first row (row = bid; GRID < N_ROWS always) ----
    float4 c[4];
    int4   tv[4];
    {
        const float4* __restrict__ crow =
            reinterpret_cast<const float4*>(cossim + (size_t)bid * N_COLS);
        const int4* __restrict__ trow =
            reinterpret_cast<const int4*>(target + (size_t)bid * N_COLS);
#pragma unroll
        for (int k = 0; k < 4; k++) c[k]  = crow[k * THREADS + t];
#pragma unroll
        for (int k = 0; k < 4; k++) tv[k] = trow[k * THREADS + t];
    }

    float acc = 0.0f;
    int nrows = 0;
    int par = 0;

#pragma unroll 1
    for (int r = bid; r < N_ROWS; r += GRID, par ^= 1) {
        nrows++;

        // ---- 1) Scan current target regs (ALU only; tv dies here) ----
        float corr_local = 0.0f;
        bool found = false;
#pragma unroll
        for (int k = 0; k < 4; k++) {
            if (tv[k].x == 1) { corr_local = c[k].x; found = true; }
            if (tv[k].y == 1) { corr_local = c[k].y; found = true; }
            if (tv[k].z == 1) { corr_local = c[k].z; found = true; }
            if (tv[k].w == 1) { corr_local = c[k].w; found = true; }
        }

        // ---- 2) Issue NEXT row's loads (in flight across barrier+compute) ----
        float4 cn[4];
        int4   tn[4];
        const int rn = r + GRID;
        if (rn < N_ROWS) {
            const float4* __restrict__ crow =
                reinterpret_cast<const float4*>(cossim + (size_t)rn * N_COLS);
            const int4* __restrict__ trow =
                reinterpret_cast<const int4*>(target + (size_t)rn * N_COLS);
#pragma unroll
            for (int k = 0; k < 4; k++) cn[k] = crow[k * THREADS + t];
#pragma unroll
            for (int k = 0; k < 4; k++) tn[k] = trow[k * THREADS + t];
        }

        // ---- 3) Broadcast corr (parity double-buffered, one barrier) ----
        if (found) s_corr[par] = corr_local;
        __syncthreads();
        const float corr = s_corr[par];

        // ---- 4) Hinge on current row's register-held cossim ----
        // (correct column contributes exactly MARGIN; removed per-CTA at end)
        float sum = 0.0f;
#pragma unroll
        for (int k = 0; k < 4; k++) {
            sum += fmaxf(MARGIN + c[k].x - corr, 0.0f);
            sum += fmaxf(MARGIN + c[k].y - corr, 0.0f);
            sum += fmaxf(MARGIN + c[k].z - corr, 0.0f);
            sum += fmaxf(MARGIN + c[k].w - corr, 0.0f);
        }
        acc += sum;

        // ---- 5) Rotate pipeline ----
#pragma unroll
        for (int k = 0; k < 4; k++) { c[k] = cn[k]; tv[k] = tn[k]; }
    }

    // ---- Block reduce per-CTA accumulator ----
#pragma unroll
    for (int off = 16; off > 0; off >>= 1)
        acc += __shfl_down_sync(0xffffffffu, acc, off);
    if (lane == 0) s_warp[wid] = acc;
    __syncthreads();

    if (t == 0) {
        float v = s_warp[0];
#pragma unroll
        for (int w = 1; w < NWARP; w++) v += s_warp[w];
        g_partial[bid] = v - (float)nrows * MARGIN;
        __threadfence();
        s_ticket = atomicAdd(&g_count, 1u);
    }
    __syncthreads();

    // ---- Last CTA: deterministic final reduction of GRID partials ----
    if (s_ticket == (unsigned int)(GRID - 1)) {
        __threadfence();

        float s = 0.0f;
        for (int i = t; i < GRID; i += THREADS)
            s += __ldcg(&g_partial[i]);

#pragma unroll
        for (int off = 16; off > 0; off >>= 1)
            s += __shfl_down_sync(0xffffffffu, s, off);
        if (lane == 0) s_warp[wid] = s;
        __syncthreads();

        if (t == 0) {
            float v = s_warp[0];
#pragma unroll
            for (int w = 1; w < NWARP; w++) v += s_warp[w];
            out[0] = v * (1.0f / (float)N_ROWS);
            g_count = 0;   // reset for next graph replay
        }
    }
}

extern "C" void kernel_launch(void* const* d_in, const int* in_sizes, int n_in,
                              void* d_out, int out_size)
{
    const float* cossim = (const float*)d_in[0];
    const int*   target = (const int*)d_in[1];
    float* out = (float*)d_out;

    mm_pipe_kernel<<<GRID, THREADS>>>(cossim, target, out);
}